// round 14
// baseline (speedup 1.0000x reference)
#include <cuda_runtime.h>
#include <cuda_fp16.h>
#include <cstdint>

#define NB   16
#define CIN  256
#define CR   64
#define HWSZ 2304
#define NJT  18            // 2304 / 128 j tiles (attn)
#define NITA 18            // attn i tiles of 128

// exp path: e = exp2(p*log2e - 11) = exp(p) * 2^-11 (P scale folded into exponent)
// att stored fp16 with extra 2^-4; lsum sums e (scaled 2^-11) -> oscale = 16/Sp
#define ASCALE  0.0625f

// ---------------- scratch (device globals; no allocation allowed) ----------
__device__ __half g_xh [NB*CIN*HWSZ];                      // x fp16
__device__ __half g_qT [NB*HWSZ*CR];                       // [n][pos][c]
__device__ __half g_kT [NB*HWSZ*CR];                       // [n][pos][c]
__device__ __half g_vh [NB*CR*HWSZ];                       // [n][c][pos]
__device__ __half g_attF[NB*HWSZ*CR];                      // [n][pos][c], x2^-15
__device__ float  g_partial[NB*NJT];

// ---------------- helpers (sm_80-level PTX only) ----------------------------
__device__ __forceinline__ uint32_t smem_u32(const void* p) {
    uint32_t a;
    asm("{ .reg .u64 t; cvta.to.shared.u64 t, %1; cvt.u32.u64 %0, t; }" : "=r"(a) : "l"(p));
    return a;
}
__device__ __forceinline__ void mma16816(float* d, const uint32_t* a, const uint32_t* b) {
    asm volatile("mma.sync.aligned.m16n8k16.row.col.f32.f16.f16.f32 "
        "{%0,%1,%2,%3}, {%4,%5,%6,%7}, {%8,%9}, {%0,%1,%2,%3};"
        : "+f"(d[0]), "+f"(d[1]), "+f"(d[2]), "+f"(d[3])
        : "r"(a[0]), "r"(a[1]), "r"(a[2]), "r"(a[3]), "r"(b[0]), "r"(b[1]));
}
__device__ __forceinline__ void ldsm_x4(uint32_t* r, uint32_t addr) {
    asm volatile("ldmatrix.sync.aligned.m8n8.x4.shared.b16 {%0,%1,%2,%3}, [%4];"
        : "=r"(r[0]), "=r"(r[1]), "=r"(r[2]), "=r"(r[3]) : "r"(addr));
}
__device__ __forceinline__ void ldsm_x4_t(uint32_t* r, uint32_t addr) {
    asm volatile("ldmatrix.sync.aligned.m8n8.x4.trans.shared.b16 {%0,%1,%2,%3}, [%4];"
        : "=r"(r[0]), "=r"(r[1]), "=r"(r[2]), "=r"(r[3]) : "r"(addr));
}
__device__ __forceinline__ void ldsm_x2(uint32_t* r, uint32_t addr) {
    asm volatile("ldmatrix.sync.aligned.m8n8.x2.shared.b16 {%0,%1}, [%2];"
        : "=r"(r[0]), "=r"(r[1]) : "r"(addr));
}
__device__ __forceinline__ void ldsm_x2_t(uint32_t* r, uint32_t addr) {
    asm volatile("ldmatrix.sync.aligned.m8n8.x2.trans.shared.b16 {%0,%1}, [%2];"
        : "=r"(r[0]), "=r"(r[1]) : "r"(addr));
}
__device__ __forceinline__ void cpa16(uint32_t dst, const void* src) {
    asm volatile("cp.async.cg.shared.global [%0], [%1], 16;" :: "r"(dst), "l"(src));
}
#define CPA_COMMIT() asm volatile("cp.async.commit_group;" ::: "memory")
#define CPA_WAIT0()  asm volatile("cp.async.wait_group 0;" ::: "memory")
#define CPA_WAIT1()  asm volatile("cp.async.wait_group 1;" ::: "memory")
__device__ __forceinline__ uint32_t pack_h2(float lo, float hi) {
    uint32_t r;
    asm("cvt.rn.f16x2.f32 %0, %1, %2;" : "=r"(r) : "f"(hi), "f"(lo));
    return r;
}
__device__ __forceinline__ uint32_t ex2_h2(uint32_t h) {
    uint32_t r;
    asm("ex2.approx.f16x2 %0, %1;" : "=r"(r) : "r"(h));
    return r;
}

// ---------------------------------------------------------------------------
// Kernel 0: x fp32 -> fp16, same [n][ci][p] layout. 8 elems/thread.
// ---------------------------------------------------------------------------
__global__ __launch_bounds__(256) void convert_kernel(const float* __restrict__ x)
{
    size_t i = ((size_t)blockIdx.x * 256 + threadIdx.x) * 8;
    float4 v0 = *(const float4*)(x + i);
    float4 v1 = *(const float4*)(x + i + 4);
    uint4 o;
    o.x = pack_h2(v0.x, v0.y);
    o.y = pack_h2(v0.z, v0.w);
    o.z = pack_h2(v1.x, v1.y);
    o.w = pack_h2(v1.z, v1.w);
    *(uint4*)&g_xh[i] = o;
}

// ---------------------------------------------------------------------------
// Kernel 1: HMMA QKV projection (single fp16).
//  which 0/1 (q,k): C[p][c] = x^T W^T, written transposed [pos][c]
//  which 2   (v)  : C[c][p] = W x,     written [c][pos]
// ---------------------------------------------------------------------------
#define XSTR 528
#define OFF_BIAS 0
#define OFF_WH   512
#define OFF_X    (OFF_WH + 64*XSTR)
#define XBUF(b)  (OFF_X + (b) * 64*XSTR)
#define QKV_SMEM (OFF_X + 2*64*XSTR)   // 101888

__global__ __launch_bounds__(256, 1) void qkv_hmma(
    const float* __restrict__ Wq, const float* __restrict__ bq,
    const float* __restrict__ Wk, const float* __restrict__ bk,
    const float* __restrict__ Wv, const float* __restrict__ bv)
{
    extern __shared__ char sm[];
    const uint32_t sb = smem_u32(sm);
    const int tid = threadIdx.x, wid = tid >> 5, lane = tid & 31;
    const int n = blockIdx.y, p0 = blockIdx.x * 256, which = blockIdx.z;

    const float* W = (which == 0) ? Wq : (which == 1) ? Wk : Wv;
    const float* b = (which == 0) ? bq : (which == 1) ? bk : bv;

    if (tid < 64) ((float*)(sm + OFF_BIAS))[tid] = b[tid];
    for (int t = tid; t < 64*256; t += 256) {
        int c = t >> 8, ci = t & 255;
        *(__half*)(sm + OFF_WH + c*XSTR + ci*2) = __float2half_rn(W[t]);
    }

    #define LOAD_X(KK, BUF) do {                                                      \
        for (int t = tid; t < 2048; t += 256) {                                       \
            int r = t >> 5, ch = t & 31;                                              \
            const char* src = (const char*)g_xh                                       \
                + ((size_t)(n*CIN + (KK)*64 + r)*HWSZ + p0)*2 + ch*16;                \
            cpa16(sb + XBUF(BUF) + r*XSTR + ch*16, src);                              \
        }                                                                             \
    } while (0)

    LOAD_X(0, 0);
    CPA_COMMIT();

    float acc[16][4];
    #pragma unroll
    for (int t = 0; t < 16; t++)
        #pragma unroll
        for (int r = 0; r < 4; r++) acc[t][r] = 0.f;

    for (int kk = 0; kk < 4; kk++) {
        const int buf = kk & 1;
        if (kk < 3) { LOAD_X(kk + 1, buf ^ 1); CPA_COMMIT(); CPA_WAIT1(); }
        else        { CPA_WAIT0(); }
        __syncthreads();

        const uint32_t xh = sb + XBUF(buf);

        if (which < 2) {
            #pragma unroll
            for (int k = 0; k < 4; k++) {
                const int ci = kk*64 + k*16;
                uint32_t bh[8][2];
                #pragma unroll
                for (int ni = 0; ni < 8; ni++) {
                    uint32_t a = (ni*8 + (lane&7))*XSTR + (ci + ((lane>>3)&1)*8)*2;
                    ldsm_x2(bh[ni], sb + OFF_WH + a);
                }
                #pragma unroll
                for (int mi = 0; mi < 2; mi++) {
                    uint32_t aH[4];
                    uint32_t ar = k*16 + (lane&7) + ((lane>>4)<<3);
                    uint32_t ac = wid*32 + mi*16 + ((lane>>3)&1)*8;
                    ldsm_x4_t(aH, xh + ar*XSTR + ac*2);
                    #pragma unroll
                    for (int ni = 0; ni < 8; ni++)
                        mma16816(acc[mi*8+ni], aH, bh[ni]);
                }
            }
        } else {
            #pragma unroll
            for (int k = 0; k < 4; k++) {
                const int ci = kk*64 + k*16;
                uint32_t bxh[4][2];
                #pragma unroll
                for (int ni = 0; ni < 4; ni++) {
                    uint32_t a = (k*16 + (lane&7) + ((lane>>3)&1)*8)*XSTR
                               + (wid*32 + ni*8)*2;
                    ldsm_x2_t(bxh[ni], xh + a);
                }
                #pragma unroll
                for (int mi = 0; mi < 4; mi++) {
                    uint32_t aH[4];
                    uint32_t a = (mi*16 + (lane&15))*XSTR + (ci + (lane>>4)*8)*2;
                    ldsm_x4(aH, sb + OFF_WH + a);
                    #pragma unroll
                    for (int ni = 0; ni < 4; ni++)
                        mma16816(acc[mi*4+ni], aH, bxh[ni]);
                }
            }
        }
        __syncthreads();
    }

    const float* sBias = (const float*)(sm + OFF_BIAS);

    if (which < 2) {
        __half* oh = (which == 0) ? g_qT : g_kT;
        char* stg = sm + XBUF(0) + wid*4608;
        #pragma unroll
        for (int mi = 0; mi < 2; mi++)
            #pragma unroll
            for (int ni = 0; ni < 8; ni++) {
                float b0 = sBias[ni*8 + (lane&3)*2];
                float b1 = sBias[ni*8 + (lane&3)*2 + 1];
                const float* d = acc[mi*8+ni];
                uint32_t u0 = pack_h2(d[0]+b0, d[1]+b1);
                uint32_t u1 = pack_h2(d[2]+b0, d[3]+b1);
                uint32_t cb = (ni*8 + (lane&3)*2)*2;
                *(uint32_t*)(stg + (mi*16 + (lane>>2))*144 + cb)     = u0;
                *(uint32_t*)(stg + (mi*16 + (lane>>2) + 8)*144 + cb) = u1;
            }
        __syncwarp();
        #pragma unroll
        for (int i = 0; i < 8; i++) {
            int chunk = i*32 + lane, row = chunk >> 3, off = chunk & 7;
            uint4 v = *(uint4*)(stg + row*144 + off*16);
            *(uint4*)&oh[((size_t)n*HWSZ + p0 + wid*32 + row)*CR + off*8] = v;
        }
    } else {
        #pragma unroll
        for (int mi = 0; mi < 4; mi++) {
            int c0 = mi*16 + (lane>>2), c1 = c0 + 8;
            float b0 = sBias[c0], b1 = sBias[c1];
            #pragma unroll
            for (int ni = 0; ni < 4; ni++) {
                const float* d = acc[mi*4+ni];
                size_t p = (size_t)p0 + wid*32 + ni*8 + (lane&3)*2;
                *(uint32_t*)&g_vh[((size_t)n*CR + c0)*HWSZ + p] = pack_h2(d[0]+b0, d[1]+b0);
                *(uint32_t*)&g_vh[((size_t)n*CR + c1)*HWSZ + p] = pack_h2(d[2]+b1, d[3]+b1);
            }
        }
    }
}

// ---------------------------------------------------------------------------
// Kernel 2: FA2-style HMMA attention.
//   MMA1: P = Q^T K -> ex2.f16x2(p*log2e - 11)  (exp & 2^-11 scale fused)
//   MMA2: attT += P V^T  (P A-frag direct from registers)
// ldsm_x4 for K and V fragments (half the LDSM count). 2 CTAs/SM.
// ---------------------------------------------------------------------------
#define QSTRIDE 144
#define VSTRIDE 272
#define SM_RED  0
#define SM_QH   128
#define SM_KH   (SM_QH + 128*QSTRIDE)
#define SM_VH   (SM_KH + 2*128*QSTRIDE)
#define SM_TOT  (SM_VH + 2*64*VSTRIDE)     // 90240

__global__ __launch_bounds__(256, 2) void attn_kernel()
{
    extern __shared__ char smem[];
    const uint32_t sb = smem_u32(smem);
    const int tid = threadIdx.x, wid = tid >> 5, lane = tid & 31;
    const int n = blockIdx.y, j0 = blockIdx.x * 128;

    {
        const char* qh = (const char*)(g_qT + ((size_t)n*HWSZ + j0)*CR);
        for (int t = tid; t < 1024; t += 256) {
            int row = t >> 3, ch = t & 7;
            cpa16(sb + SM_QH + row*QSTRIDE + ch*16, qh + row*128 + ch*16);
        }
    }
    const char* khg = (const char*)(g_kT + (size_t)n*HWSZ*CR);
    const char* vhg = (const char*)(g_vh + (size_t)n*CR*HWSZ);

    #define LOAD_KV(IT, BUF) do {                                                   \
        const int _i0 = (IT) * 128;                                                 \
        const uint32_t _kh = sb + SM_KH + (BUF)*128*QSTRIDE;                         \
        for (int t = tid; t < 1024; t += 256) {                                      \
            int row = t >> 3, ch = t & 7;                                            \
            cpa16(_kh + row*QSTRIDE + ch*16, khg + ((size_t)(_i0+row)*CR)*2 + ch*16);\
        }                                                                            \
        const uint32_t _vh = sb + SM_VH + (BUF)*64*VSTRIDE;                          \
        for (int t = tid; t < 1024; t += 256) {                                      \
            int c = t >> 4, ch = t & 15;                                             \
            cpa16(_vh + c*VSTRIDE + ch*16, vhg + ((size_t)c*HWSZ + _i0)*2 + ch*16);  \
        }                                                                            \
    } while (0)

    LOAD_KV(0, 0);
    CPA_COMMIT();
    CPA_WAIT0();
    __syncthreads();

    uint32_t qf[4][4];
    {
        const int jrow = wid*16 + (lane & 15);
        const int coff = ((lane >> 4) << 3);
        #pragma unroll
        for (int k = 0; k < 4; k++)
            ldsm_x4(qf[k], sb + SM_QH + jrow*QSTRIDE + (k*16 + coff)*2);
    }

    float accO[8][4];
    #pragma unroll
    for (int t = 0; t < 8; t++)
        #pragma unroll
        for (int r = 0; r < 4; r++) accO[t][r] = 0.f;
    float lsum = 0.f;

    // ldmatrix x4 lane-address components (same for K and V frags)
    const uint32_t l_row  = ((lane >> 4) << 3) + (lane & 7);   // row within 16
    const uint32_t l_half = ((lane >> 3) & 1) * 8;             // k-half select
    const float L2E = 1.44269504f;

    #pragma unroll 1
    for (int it = 0; it < NITA; it++) {
        const int buf = it & 1;
        if (it + 1 < NITA) { LOAD_KV(it + 1, buf ^ 1); CPA_COMMIT(); CPA_WAIT1(); }
        else               { CPA_WAIT0(); }
        __syncthreads();

        const uint32_t khb = sb + SM_KH + buf*128*QSTRIDE;
        const uint32_t vhb = sb + SM_VH + buf*64*VSTRIDE;

        #pragma unroll
        for (int ic = 0; ic < 8; ic++) {
            // K frags: one x4 per k-step covers both n-tiles (nt0={r0,r1}, nt1={r2,r3})
            uint32_t bk4[4][4];
            #pragma unroll
            for (int k = 0; k < 4; k++)
                ldsm_x4(bk4[k], khb + (ic*16 + l_row)*QSTRIDE + (k*16 + l_half)*2);

            float pacc[2][4];
            #pragma unroll
            for (int nt = 0; nt < 2; nt++)
                #pragma unroll
                for (int r = 0; r < 4; r++) pacc[nt][r] = 0.f;

            #pragma unroll
            for (int k = 0; k < 4; k++) {
                mma16816(pacc[0], qf[k], &bk4[k][0]);
                mma16816(pacc[1], qf[k], &bk4[k][2]);
            }

            // exp: e = exp2(p*log2e - 11), computed as fp16x2 MUFU
            uint32_t af[4];
            #pragma unroll
            for (int nt = 0; nt < 2; nt++)
                #pragma unroll
                for (int g = 0; g < 2; g++) {
                    float t0 = fmaf(pacc[nt][g*2],   L2E, -11.f);
                    float t1 = fmaf(pacc[nt][g*2+1], L2E, -11.f);
                    af[nt*2+g] = ex2_h2(pack_h2(t0, t1));
                }
            // lsum via h2 adds
            {
                __half2 s = __hadd2(
                    __hadd2(*(__half2*)&af[0], *(__half2*)&af[1]),
                    __hadd2(*(__half2*)&af[2], *(__half2*)&af[3]));
                float2 f = __half22float2(s);
                lsum += f.x + f.y;
            }

            // V frags + MMA2: one x4 per nt2-pair
            #pragma unroll
            for (int t = 0; t < 4; t++) {
                uint32_t bv4[4];
                ldsm_x4(bv4, vhb + (t*16 + l_row)*VSTRIDE + (ic*16 + l_half)*2);
                mma16816(accO[t*2],     af, &bv4[0]);
                mma16816(accO[t*2 + 1], af, &bv4[2]);
            }
        }
        __syncthreads();
    }

    // write attT as fp16 (accO already x2^-11; extra x2^-4 -> total 2^-15)
    {
        int r0 = j0 + wid*16 + (lane >> 2);
        int c0 = (lane & 3) * 2;
        __half* base0 = g_attF + ((size_t)n*HWSZ + r0)*CR;
        __half* base1 = base0 + 8*CR;
        #pragma unroll
        for (int nt2 = 0; nt2 < 8; nt2++) {
            *(uint32_t*)&base0[nt2*8 + c0] = pack_h2(accO[nt2][0]*ASCALE, accO[nt2][1]*ASCALE);
            *(uint32_t*)&base1[nt2*8 + c0] = pack_h2(accO[nt2][2]*ASCALE, accO[nt2][3]*ASCALE);
        }
    }

    #pragma unroll
    for (int off = 16; off > 0; off >>= 1)
        lsum += __shfl_xor_sync(0xFFFFFFFFu, lsum, off);
    if (lane == 0) ((float*)(smem + SM_RED))[wid] = lsum;
    __syncthreads();
    if (tid == 0) {
        float s = 0.f;
        #pragma unroll
        for (int w = 0; w < 8; w++) s += ((float*)(smem + SM_RED))[w];
        g_partial[n*NJT + blockIdx.x] = s;   // = S_true * 2^-11
    }
}

// ---------------------------------------------------------------------------
// Kernel 3: HMMA output conv + normalize + residual.
// out[o][p] = gco * (Watt@attF * 16/Sp + batt + 1)   (Sp = S*2^-11; attF = att*2^-15)
// Tile 64o x 128p, grid (18, 4, 16), 2 CTAs/SM, direct float2 epilogue.
// ---------------------------------------------------------------------------
#define OW_STR 144
#define OO_S   0
#define OO_B   16
#define OO_W   288
#define OO_A   (OO_W + 64*OW_STR)          // 9504
#define OUT_SMEM (OO_A + 128*OW_STR)       // 27936

__global__ __launch_bounds__(256, 2) void out_hmma(
    const float* __restrict__ gco,
    const float* __restrict__ Watt, const float* __restrict__ batt,
    float* __restrict__ out)
{
    extern __shared__ char sm[];
    const uint32_t sb = smem_u32(sm);
    const int tid = threadIdx.x, wid = tid >> 5, lane = tid & 31;
    const int n = blockIdx.z, o0 = blockIdx.y * 64, p0 = blockIdx.x * 128;

    if (tid == 0) {
        float s = 0.f;
        #pragma unroll
        for (int t = 0; t < NJT; t++) s += g_partial[n*NJT + t];
        *(float*)(sm + OO_S) = 16.0f / s;
    }
    if (tid < 64) ((float*)(sm + OO_B))[tid] = batt[o0 + tid];
    // Watt slice fp32 -> fp16 smem [o][c]
    for (int t = tid; t < 64*64; t += 256) {
        int o = t >> 6, c = t & 63;
        *(__half*)(sm + OO_W + o*OW_STR + c*2) =
            __float2half_rn(Watt[(size_t)(o0 + o)*CR + c]);
    }
    // att fp16 -> smem [p][c]
    {
        const char* ag = (const char*)(g_attF + ((size_t)n*HWSZ + p0)*CR);
        for (int t = tid; t < 1024; t += 256) {
            int r = t >> 3, ch = t & 7;
            cpa16(sb + OO_A + r*OW_STR + ch*16, ag + r*128 + ch*16);
        }
    }
    CPA_COMMIT();
    CPA_WAIT0();
    __syncthreads();

    const int wo = wid & 1, wp = wid >> 1;   // 2 warps over o(32), 4 over p(32)
    const uint32_t l_row  = ((lane >> 4) << 3) + (lane & 7);
    const uint32_t l_half = ((lane >> 3) & 1) * 8;

    float acc[8][4];
    #pragma unroll
    for (int t = 0; t < 8; t++)
        #pragma unroll
        for (int r = 0; r < 4; r++) acc[t][r] = 0.f;

    #pragma unroll
    for (int k = 0; k < 4; k++) {
        uint32_t bA[8];
        #pragma unroll
        for (int t2 = 0; t2 < 2; t2++)
            ldsm_x4(&bA[t2*4], sb + OO_A + (wp*32 + t2*16 + l_row)*OW_STR
                                         + (k*16 + l_half)*2);
        #pragma unroll
        for (int mi = 0; mi < 2; mi++) {
            uint32_t aW[4];
            ldsm_x4(aW, sb + OO_W + (wo*32 + mi*16 + (lane&15))*OW_STR
                                  + (k*16 + ((lane>>4)<<3))*2);
            #pragma unroll
            for (int ni = 0; ni < 4; ni++)
                mma16816(acc[mi*4+ni], aW, &bA[ni*2]);
        }
    }

    const float oscale = *(const float*)(sm + OO_S);
    const float* sB = (const float*)(sm + OO_B);

    // direct epilogue: float2 per (row, col-pair); quads cover 32B sectors
    #pragma unroll
    for (int mi = 0; mi < 2; mi++)
        #pragma unroll
        for (int ni = 0; ni < 4; ni++) {
            const float* d = acc[mi*4+ni];
            int p = wp*32 + ni*8 + (lane&3)*2;
            #pragma unroll
            for (int h = 0; h < 2; h++) {
                int r = wo*32 + mi*16 + (lane>>2) + h*8;
                float bias = sB[r] + 1.f;
                size_t gb = ((size_t)n*CIN + o0 + r)*HWSZ + p0 + p;
                float2 g = *(const float2*)&gco[gb];
                float2 rr;
                rr.x = g.x * fmaf(d[h*2],   oscale, bias);
                rr.y = g.y * fmaf(d[h*2+1], oscale, bias);
                *(float2*)&out[gb] = rr;
            }
        }
}

// ---------------------------------------------------------------------------
extern "C" void kernel_launch(void* const* d_in, const int* in_sizes, int n_in,
                              void* d_out, int out_size)
{
    const float* x    = (const float*)d_in[0];
    const float* gco  = (const float*)d_in[1];
    const float* Wq   = (const float*)d_in[2];
    const float* bq   = (const float*)d_in[3];
    const float* Wk   = (const float*)d_in[4];
    const float* bk   = (const float*)d_in[5];
    const float* Wv   = (const float*)d_in[6];
    const float* bv   = (const float*)d_in[7];
    const float* Watt = (const float*)d_in[8];
    const float* batt = (const float*)d_in[9];
    float* out = (float*)d_out;

    cudaFuncSetAttribute(qkv_hmma,    cudaFuncAttributeMaxDynamicSharedMemorySize, QKV_SMEM);
    cudaFuncSetAttribute(attn_kernel, cudaFuncAttributeMaxDynamicSharedMemorySize, SM_TOT);

    convert_kernel<<<NB*CIN*HWSZ/2048, 256>>>(x);
    qkv_hmma<<<dim3(9, NB, 3), 256, QKV_SMEM>>>(Wq, bq, Wk, bk, Wv, bv);
    attn_kernel<<<dim3(NJT, NB), 256, SM_TOT>>>();
    out_hmma<<<dim3(18, 4, NB), 256, OUT_SMEM>>>(gco, Watt, batt, out);
}

// round 15
// speedup vs baseline: 1.0335x; 1.0335x over previous
#include <cuda_runtime.h>
#include <cuda_fp16.h>
#include <cstdint>

#define NB   16
#define CIN  256
#define CR   64
#define HWSZ 2304
#define NJT  18            // 2304 / 128 j tiles (attn)
#define NITA 18            // attn i tiles of 128

// exp path: e = exp2(p*log2e - 11) = exp(p) * 2^-11 (P scale folded into exponent)
// att stored fp16 with extra 2^-4; lsum sums e (scaled 2^-11) -> oscale = 16/Sp
#define ASCALE  0.0625f

// ---------------- scratch (device globals; no allocation allowed) ----------
__device__ __half g_xh [NB*CIN*HWSZ];                      // x fp16
__device__ __half g_qT [NB*HWSZ*CR];                       // [n][pos][c]
__device__ __half g_kT [NB*HWSZ*CR];                       // [n][pos][c]
__device__ __half g_vh [NB*CR*HWSZ];                       // [n][c][pos]
__device__ __half g_attF[NB*HWSZ*CR];                      // [n][pos][c], x2^-15
__device__ float  g_partial[NB*NJT];

// ---------------- helpers (sm_80-level PTX only) ----------------------------
__device__ __forceinline__ uint32_t smem_u32(const void* p) {
    uint32_t a;
    asm("{ .reg .u64 t; cvta.to.shared.u64 t, %1; cvt.u32.u64 %0, t; }" : "=r"(a) : "l"(p));
    return a;
}
__device__ __forceinline__ void mma16816(float* d, const uint32_t* a, const uint32_t* b) {
    asm volatile("mma.sync.aligned.m16n8k16.row.col.f32.f16.f16.f32 "
        "{%0,%1,%2,%3}, {%4,%5,%6,%7}, {%8,%9}, {%0,%1,%2,%3};"
        : "+f"(d[0]), "+f"(d[1]), "+f"(d[2]), "+f"(d[3])
        : "r"(a[0]), "r"(a[1]), "r"(a[2]), "r"(a[3]), "r"(b[0]), "r"(b[1]));
}
__device__ __forceinline__ void ldsm_x4(uint32_t* r, uint32_t addr) {
    asm volatile("ldmatrix.sync.aligned.m8n8.x4.shared.b16 {%0,%1,%2,%3}, [%4];"
        : "=r"(r[0]), "=r"(r[1]), "=r"(r[2]), "=r"(r[3]) : "r"(addr));
}
__device__ __forceinline__ void ldsm_x4_t(uint32_t* r, uint32_t addr) {
    asm volatile("ldmatrix.sync.aligned.m8n8.x4.trans.shared.b16 {%0,%1,%2,%3}, [%4];"
        : "=r"(r[0]), "=r"(r[1]), "=r"(r[2]), "=r"(r[3]) : "r"(addr));
}
__device__ __forceinline__ void ldsm_x2(uint32_t* r, uint32_t addr) {
    asm volatile("ldmatrix.sync.aligned.m8n8.x2.shared.b16 {%0,%1}, [%2];"
        : "=r"(r[0]), "=r"(r[1]) : "r"(addr));
}
__device__ __forceinline__ void ldsm_x2_t(uint32_t* r, uint32_t addr) {
    asm volatile("ldmatrix.sync.aligned.m8n8.x2.trans.shared.b16 {%0,%1}, [%2];"
        : "=r"(r[0]), "=r"(r[1]) : "r"(addr));
}
__device__ __forceinline__ void cpa16(uint32_t dst, const void* src) {
    asm volatile("cp.async.cg.shared.global [%0], [%1], 16;" :: "r"(dst), "l"(src));
}
#define CPA_COMMIT() asm volatile("cp.async.commit_group;" ::: "memory")
#define CPA_WAIT0()  asm volatile("cp.async.wait_group 0;" ::: "memory")
#define CPA_WAIT1()  asm volatile("cp.async.wait_group 1;" ::: "memory")
__device__ __forceinline__ uint32_t pack_h2(float lo, float hi) {
    uint32_t r;
    asm("cvt.rn.f16x2.f32 %0, %1, %2;" : "=r"(r) : "f"(hi), "f"(lo));
    return r;
}
__device__ __forceinline__ uint32_t ex2_h2(uint32_t h) {
    uint32_t r;
    asm("ex2.approx.f16x2 %0, %1;" : "=r"(r) : "r"(h));
    return r;
}

// ---------------------------------------------------------------------------
// Kernel 0: x fp32 -> fp16, same [n][ci][p] layout. 8 elems/thread.
// ---------------------------------------------------------------------------
__global__ __launch_bounds__(256) void convert_kernel(const float* __restrict__ x)
{
    size_t i = ((size_t)blockIdx.x * 256 + threadIdx.x) * 8;
    float4 v0 = *(const float4*)(x + i);
    float4 v1 = *(const float4*)(x + i + 4);
    uint4 o;
    o.x = pack_h2(v0.x, v0.y);
    o.y = pack_h2(v0.z, v0.w);
    o.z = pack_h2(v1.x, v1.y);
    o.w = pack_h2(v1.z, v1.w);
    *(uint4*)&g_xh[i] = o;
}

// ---------------------------------------------------------------------------
// Kernel 1: HMMA QKV projection (single fp16).
//  which 0/1 (q,k): C[p][c] = x^T W^T, written transposed [pos][c]
//  which 2   (v)  : C[c][p] = W x,     written [c][pos]
// ---------------------------------------------------------------------------
#define XSTR 528
#define OFF_BIAS 0
#define OFF_WH   512
#define OFF_X    (OFF_WH + 64*XSTR)
#define XBUF(b)  (OFF_X + (b) * 64*XSTR)
#define QKV_SMEM (OFF_X + 2*64*XSTR)   // 101888

__global__ __launch_bounds__(256, 1) void qkv_hmma(
    const float* __restrict__ Wq, const float* __restrict__ bq,
    const float* __restrict__ Wk, const float* __restrict__ bk,
    const float* __restrict__ Wv, const float* __restrict__ bv)
{
    extern __shared__ char sm[];
    const uint32_t sb = smem_u32(sm);
    const int tid = threadIdx.x, wid = tid >> 5, lane = tid & 31;
    const int n = blockIdx.y, p0 = blockIdx.x * 256, which = blockIdx.z;

    const float* W = (which == 0) ? Wq : (which == 1) ? Wk : Wv;
    const float* b = (which == 0) ? bq : (which == 1) ? bk : bv;

    if (tid < 64) ((float*)(sm + OFF_BIAS))[tid] = b[tid];
    for (int t = tid; t < 64*256; t += 256) {
        int c = t >> 8, ci = t & 255;
        *(__half*)(sm + OFF_WH + c*XSTR + ci*2) = __float2half_rn(W[t]);
    }

    #define LOAD_X(KK, BUF) do {                                                      \
        for (int t = tid; t < 2048; t += 256) {                                       \
            int r = t >> 5, ch = t & 31;                                              \
            const char* src = (const char*)g_xh                                       \
                + ((size_t)(n*CIN + (KK)*64 + r)*HWSZ + p0)*2 + ch*16;                \
            cpa16(sb + XBUF(BUF) + r*XSTR + ch*16, src);                              \
        }                                                                             \
    } while (0)

    LOAD_X(0, 0);
    CPA_COMMIT();

    float acc[16][4];
    #pragma unroll
    for (int t = 0; t < 16; t++)
        #pragma unroll
        for (int r = 0; r < 4; r++) acc[t][r] = 0.f;

    for (int kk = 0; kk < 4; kk++) {
        const int buf = kk & 1;
        if (kk < 3) { LOAD_X(kk + 1, buf ^ 1); CPA_COMMIT(); CPA_WAIT1(); }
        else        { CPA_WAIT0(); }
        __syncthreads();

        const uint32_t xh = sb + XBUF(buf);

        if (which < 2) {
            #pragma unroll
            for (int k = 0; k < 4; k++) {
                const int ci = kk*64 + k*16;
                uint32_t bh[8][2];
                #pragma unroll
                for (int ni = 0; ni < 8; ni++) {
                    uint32_t a = (ni*8 + (lane&7))*XSTR + (ci + ((lane>>3)&1)*8)*2;
                    ldsm_x2(bh[ni], sb + OFF_WH + a);
                }
                #pragma unroll
                for (int mi = 0; mi < 2; mi++) {
                    uint32_t aH[4];
                    uint32_t ar = k*16 + (lane&7) + ((lane>>4)<<3);
                    uint32_t ac = wid*32 + mi*16 + ((lane>>3)&1)*8;
                    ldsm_x4_t(aH, xh + ar*XSTR + ac*2);
                    #pragma unroll
                    for (int ni = 0; ni < 8; ni++)
                        mma16816(acc[mi*8+ni], aH, bh[ni]);
                }
            }
        } else {
            #pragma unroll
            for (int k = 0; k < 4; k++) {
                const int ci = kk*64 + k*16;
                uint32_t bxh[4][2];
                #pragma unroll
                for (int ni = 0; ni < 4; ni++) {
                    uint32_t a = (k*16 + (lane&7) + ((lane>>3)&1)*8)*XSTR
                               + (wid*32 + ni*8)*2;
                    ldsm_x2_t(bxh[ni], xh + a);
                }
                #pragma unroll
                for (int mi = 0; mi < 4; mi++) {
                    uint32_t aH[4];
                    uint32_t a = (mi*16 + (lane&15))*XSTR + (ci + (lane>>4)*8)*2;
                    ldsm_x4(aH, sb + OFF_WH + a);
                    #pragma unroll
                    for (int ni = 0; ni < 4; ni++)
                        mma16816(acc[mi*4+ni], aH, bxh[ni]);
                }
            }
        }
        __syncthreads();
    }

    const float* sBias = (const float*)(sm + OFF_BIAS);

    if (which < 2) {
        __half* oh = (which == 0) ? g_qT : g_kT;
        char* stg = sm + XBUF(0) + wid*4608;
        #pragma unroll
        for (int mi = 0; mi < 2; mi++)
            #pragma unroll
            for (int ni = 0; ni < 8; ni++) {
                float b0 = sBias[ni*8 + (lane&3)*2];
                float b1 = sBias[ni*8 + (lane&3)*2 + 1];
                const float* d = acc[mi*8+ni];
                uint32_t u0 = pack_h2(d[0]+b0, d[1]+b1);
                uint32_t u1 = pack_h2(d[2]+b0, d[3]+b1);
                uint32_t cb = (ni*8 + (lane&3)*2)*2;
                *(uint32_t*)(stg + (mi*16 + (lane>>2))*144 + cb)     = u0;
                *(uint32_t*)(stg + (mi*16 + (lane>>2) + 8)*144 + cb) = u1;
            }
        __syncwarp();
        #pragma unroll
        for (int i = 0; i < 8; i++) {
            int chunk = i*32 + lane, row = chunk >> 3, off = chunk & 7;
            uint4 v = *(uint4*)(stg + row*144 + off*16);
            *(uint4*)&oh[((size_t)n*HWSZ + p0 + wid*32 + row)*CR + off*8] = v;
        }
    } else {
        #pragma unroll
        for (int mi = 0; mi < 4; mi++) {
            int c0 = mi*16 + (lane>>2), c1 = c0 + 8;
            float b0 = sBias[c0], b1 = sBias[c1];
            #pragma unroll
            for (int ni = 0; ni < 4; ni++) {
                const float* d = acc[mi*4+ni];
                size_t p = (size_t)p0 + wid*32 + ni*8 + (lane&3)*2;
                *(uint32_t*)&g_vh[((size_t)n*CR + c0)*HWSZ + p] = pack_h2(d[0]+b0, d[1]+b0);
                *(uint32_t*)&g_vh[((size_t)n*CR + c1)*HWSZ + p] = pack_h2(d[2]+b1, d[3]+b1);
            }
        }
    }
}

// ---------------------------------------------------------------------------
// Kernel 2: FA2-style HMMA attention.
//   MMA1: P = Q^T K -> ex2.f16x2(p*log2e - 11)  (exp & 2^-11 scale fused)
//   MMA2: attT += P V^T  (P A-frag direct from registers)
// ldsm_x4 for K and V fragments. 2 CTAs/SM.
// ---------------------------------------------------------------------------
#define QSTRIDE 144
#define VSTRIDE 272
#define SM_RED  0
#define SM_QH   128
#define SM_KH   (SM_QH + 128*QSTRIDE)
#define SM_VH   (SM_KH + 2*128*QSTRIDE)
#define SM_TOT  (SM_VH + 2*64*VSTRIDE)     // 90240

__global__ __launch_bounds__(256, 2) void attn_kernel()
{
    extern __shared__ char smem[];
    const uint32_t sb = smem_u32(smem);
    const int tid = threadIdx.x, wid = tid >> 5, lane = tid & 31;
    const int n = blockIdx.y, j0 = blockIdx.x * 128;

    {
        const char* qh = (const char*)(g_qT + ((size_t)n*HWSZ + j0)*CR);
        for (int t = tid; t < 1024; t += 256) {
            int row = t >> 3, ch = t & 7;
            cpa16(sb + SM_QH + row*QSTRIDE + ch*16, qh + row*128 + ch*16);
        }
    }
    const char* khg = (const char*)(g_kT + (size_t)n*HWSZ*CR);
    const char* vhg = (const char*)(g_vh + (size_t)n*CR*HWSZ);

    #define LOAD_KV(IT, BUF) do {                                                   \
        const int _i0 = (IT) * 128;                                                 \
        const uint32_t _kh = sb + SM_KH + (BUF)*128*QSTRIDE;                         \
        for (int t = tid; t < 1024; t += 256) {                                      \
            int row = t >> 3, ch = t & 7;                                            \
            cpa16(_kh + row*QSTRIDE + ch*16, khg + ((size_t)(_i0+row)*CR)*2 + ch*16);\
        }                                                                            \
        const uint32_t _vh = sb + SM_VH + (BUF)*64*VSTRIDE;                          \
        for (int t = tid; t < 1024; t += 256) {                                      \
            int c = t >> 4, ch = t & 15;                                             \
            cpa16(_vh + c*VSTRIDE + ch*16, vhg + ((size_t)c*HWSZ + _i0)*2 + ch*16);  \
        }                                                                            \
    } while (0)

    LOAD_KV(0, 0);
    CPA_COMMIT();
    CPA_WAIT0();
    __syncthreads();

    uint32_t qf[4][4];
    {
        const int jrow = wid*16 + (lane & 15);
        const int coff = ((lane >> 4) << 3);
        #pragma unroll
        for (int k = 0; k < 4; k++)
            ldsm_x4(qf[k], sb + SM_QH + jrow*QSTRIDE + (k*16 + coff)*2);
    }

    float accO[8][4];
    #pragma unroll
    for (int t = 0; t < 8; t++)
        #pragma unroll
        for (int r = 0; r < 4; r++) accO[t][r] = 0.f;
    float lsum = 0.f;

    const uint32_t l_row  = ((lane >> 4) << 3) + (lane & 7);
    const uint32_t l_half = ((lane >> 3) & 1) * 8;
    const float L2E = 1.44269504f;

    #pragma unroll 1
    for (int it = 0; it < NITA; it++) {
        const int buf = it & 1;
        if (it + 1 < NITA) { LOAD_KV(it + 1, buf ^ 1); CPA_COMMIT(); CPA_WAIT1(); }
        else               { CPA_WAIT0(); }
        __syncthreads();

        const uint32_t khb = sb + SM_KH + buf*128*QSTRIDE;
        const uint32_t vhb = sb + SM_VH + buf*64*VSTRIDE;

        #pragma unroll
        for (int ic = 0; ic < 8; ic++) {
            uint32_t bk4[4][4];
            #pragma unroll
            for (int k = 0; k < 4; k++)
                ldsm_x4(bk4[k], khb + (ic*16 + l_row)*QSTRIDE + (k*16 + l_half)*2);

            float pacc[2][4];
            #pragma unroll
            for (int nt = 0; nt < 2; nt++)
                #pragma unroll
                for (int r = 0; r < 4; r++) pacc[nt][r] = 0.f;

            #pragma unroll
            for (int k = 0; k < 4; k++) {
                mma16816(pacc[0], qf[k], &bk4[k][0]);
                mma16816(pacc[1], qf[k], &bk4[k][2]);
            }

            uint32_t af[4];
            #pragma unroll
            for (int nt = 0; nt < 2; nt++)
                #pragma unroll
                for (int g = 0; g < 2; g++) {
                    float t0 = fmaf(pacc[nt][g*2],   L2E, -11.f);
                    float t1 = fmaf(pacc[nt][g*2+1], L2E, -11.f);
                    af[nt*2+g] = ex2_h2(pack_h2(t0, t1));
                }
            {
                __half2 s = __hadd2(
                    __hadd2(*(__half2*)&af[0], *(__half2*)&af[1]),
                    __hadd2(*(__half2*)&af[2], *(__half2*)&af[3]));
                float2 f = __half22float2(s);
                lsum += f.x + f.y;
            }

            #pragma unroll
            for (int t = 0; t < 4; t++) {
                uint32_t bv4[4];
                ldsm_x4(bv4, vhb + (t*16 + l_row)*VSTRIDE + (ic*16 + l_half)*2);
                mma16816(accO[t*2],     af, &bv4[0]);
                mma16816(accO[t*2 + 1], af, &bv4[2]);
            }
        }
        __syncthreads();
    }

    {
        int r0 = j0 + wid*16 + (lane >> 2);
        int c0 = (lane & 3) * 2;
        __half* base0 = g_attF + ((size_t)n*HWSZ + r0)*CR;
        __half* base1 = base0 + 8*CR;
        #pragma unroll
        for (int nt2 = 0; nt2 < 8; nt2++) {
            *(uint32_t*)&base0[nt2*8 + c0] = pack_h2(accO[nt2][0]*ASCALE, accO[nt2][1]*ASCALE);
            *(uint32_t*)&base1[nt2*8 + c0] = pack_h2(accO[nt2][2]*ASCALE, accO[nt2][3]*ASCALE);
        }
    }

    #pragma unroll
    for (int off = 16; off > 0; off >>= 1)
        lsum += __shfl_xor_sync(0xFFFFFFFFu, lsum, off);
    if (lane == 0) ((float*)(smem + SM_RED))[wid] = lsum;
    __syncthreads();
    if (tid == 0) {
        float s = 0.f;
        #pragma unroll
        for (int w = 0; w < 8; w++) s += ((float*)(smem + SM_RED))[w];
        g_partial[n*NJT + blockIdx.x] = s;   // = S_true * 2^-11
    }
}

// ---------------------------------------------------------------------------
// Kernel 3: HMMA output conv + normalize + residual.
// out[o][p] = gco * (Watt@attF * 16/Sp + batt + 1)
// Tile 64o x 128p, grid (18, 4, 16), 2 CTAs/SM.
// Epilogue: fp32 smem staging -> one warp per full 512B row (float4 coalesced).
// ---------------------------------------------------------------------------
#define OW_STR 144
#define OST_F  132                          // stage row stride in floats
#define OO_S   0
#define OO_B   16
#define OO_W   288
#define OO_A   (OO_W + 64*OW_STR)           // 9504
#define OO_ST  (OO_A + 128*OW_STR)          // 27936
#define OUT_SMEM (OO_ST + 64*OST_F*4)       // 61728

__global__ __launch_bounds__(256, 2) void out_hmma(
    const float* __restrict__ gco,
    const float* __restrict__ Watt, const float* __restrict__ batt,
    float* __restrict__ out)
{
    extern __shared__ char sm[];
    const uint32_t sb = smem_u32(sm);
    const int tid = threadIdx.x, wid = tid >> 5, lane = tid & 31;
    const int n = blockIdx.z, o0 = blockIdx.y * 64, p0 = blockIdx.x * 128;

    if (tid == 0) {
        float s = 0.f;
        #pragma unroll
        for (int t = 0; t < NJT; t++) s += g_partial[n*NJT + t];
        *(float*)(sm + OO_S) = 16.0f / s;
    }
    if (tid < 64) ((float*)(sm + OO_B))[tid] = batt[o0 + tid];
    for (int t = tid; t < 64*64; t += 256) {
        int o = t >> 6, c = t & 63;
        *(__half*)(sm + OO_W + o*OW_STR + c*2) =
            __float2half_rn(Watt[(size_t)(o0 + o)*CR + c]);
    }
    {
        const char* ag = (const char*)(g_attF + ((size_t)n*HWSZ + p0)*CR);
        for (int t = tid; t < 1024; t += 256) {
            int r = t >> 3, ch = t & 7;
            cpa16(sb + OO_A + r*OW_STR + ch*16, ag + r*128 + ch*16);
        }
    }
    CPA_COMMIT();
    CPA_WAIT0();
    __syncthreads();

    const int wo = wid & 1, wp = wid >> 1;   // 2 warps over o(32), 4 over p(32)
    const uint32_t l_row  = ((lane >> 4) << 3) + (lane & 7);
    const uint32_t l_half = ((lane >> 3) & 1) * 8;

    float acc[8][4];
    #pragma unroll
    for (int t = 0; t < 8; t++)
        #pragma unroll
        for (int r = 0; r < 4; r++) acc[t][r] = 0.f;

    #pragma unroll
    for (int k = 0; k < 4; k++) {
        uint32_t bA[8];
        #pragma unroll
        for (int t2 = 0; t2 < 2; t2++)
            ldsm_x4(&bA[t2*4], sb + OO_A + (wp*32 + t2*16 + l_row)*OW_STR
                                         + (k*16 + l_half)*2);
        #pragma unroll
        for (int mi = 0; mi < 2; mi++) {
            uint32_t aW[4];
            ldsm_x4(aW, sb + OO_W + (wo*32 + mi*16 + (lane&15))*OW_STR
                                  + (k*16 + ((lane>>4)<<3))*2);
            #pragma unroll
            for (int ni = 0; ni < 4; ni++)
                mma16816(acc[mi*4+ni], aW, &bA[ni*2]);
        }
    }

    // stage fp32 accumulators: stage[o_local][p_local], stride OST_F floats
    float* stg = (float*)(sm + OO_ST);
    #pragma unroll
    for (int mi = 0; mi < 2; mi++)
        #pragma unroll
        for (int ni = 0; ni < 4; ni++) {
            const float* d = acc[mi*4+ni];
            int c = wp*32 + ni*8 + (lane&3)*2;
            int r = wo*32 + mi*16 + (lane>>2);
            *(float2*)&stg[r*OST_F + c]       = make_float2(d[0], d[1]);
            *(float2*)&stg[(r+8)*OST_F + c]   = make_float2(d[2], d[3]);
        }
    __syncthreads();

    const float oscale = *(const float*)(sm + OO_S);
    const float* sB = (const float*)(sm + OO_B);

    // one warp = one 512B row: float4 stage read + gco read + out write
    #pragma unroll
    for (int i = 0; i < 8; i++) {
        int row = i*8 + wid;                 // local o row 0..63
        int col = lane*4;                    // local p col
        float4 a = *(float4*)&stg[row*OST_F + col];
        float bias = sB[row] + 1.f;
        size_t gb = ((size_t)n*CIN + o0 + row)*HWSZ + p0 + col;
        float4 g = *(const float4*)&gco[gb];
        float4 rr;
        rr.x = g.x * fmaf(a.x, oscale, bias);
        rr.y = g.y * fmaf(a.y, oscale, bias);
        rr.z = g.z * fmaf(a.z, oscale, bias);
        rr.w = g.w * fmaf(a.w, oscale, bias);
        *(float4*)&out[gb] = rr;
    }
}

// ---------------------------------------------------------------------------
extern "C" void kernel_launch(void* const* d_in, const int* in_sizes, int n_in,
                              void* d_out, int out_size)
{
    const float* x    = (const float*)d_in[0];
    const float* gco  = (const float*)d_in[1];
    const float* Wq   = (const float*)d_in[2];
    const float* bq   = (const float*)d_in[3];
    const float* Wk   = (const float*)d_in[4];
    const float* bk   = (const float*)d_in[5];
    const float* Wv   = (const float*)d_in[6];
    const float* bv   = (const float*)d_in[7];
    const float* Watt = (const float*)d_in[8];
    const float* batt = (const float*)d_in[9];
    float* out = (float*)d_out;

    cudaFuncSetAttribute(qkv_hmma,    cudaFuncAttributeMaxDynamicSharedMemorySize, QKV_SMEM);
    cudaFuncSetAttribute(attn_kernel, cudaFuncAttributeMaxDynamicSharedMemorySize, SM_TOT);
    cudaFuncSetAttribute(out_hmma,    cudaFuncAttributeMaxDynamicSharedMemorySize, OUT_SMEM);

    convert_kernel<<<NB*CIN*HWSZ/2048, 256>>>(x);
    qkv_hmma<<<dim3(9, NB, 3), 256, QKV_SMEM>>>(Wq, bq, Wk, bk, Wv, bv);
    attn_kernel<<<dim3(NJT, NB), 256, SM_TOT>>>();
    out_hmma<<<dim3(18, 4, NB), 256, OUT_SMEM>>>(gco, Watt, batt, out);
}

// round 16
// speedup vs baseline: 1.0490x; 1.0149x over previous
#include <cuda_runtime.h>
#include <cuda_fp16.h>
#include <cstdint>

#define NB   16
#define CIN  256
#define CR   64
#define HWSZ 2304
#define NJT  18            // 2304 / 128 j tiles (attn)
#define NITA 18            // attn i tiles of 128

// exp path: e = exp2(p*log2e - 11) = exp(p) * 2^-11 (P scale folded into exponent)
// att stored fp16 with extra 2^-4; lsum sums e (scaled 2^-11) -> oscale = 16/Sp
#define ASCALE  0.0625f

// ---------------- scratch (device globals; no allocation allowed) ----------
__device__ __half g_xh [NB*CIN*HWSZ];                      // x fp16
__device__ __half g_qT [NB*HWSZ*CR];                       // [n][pos][c]
__device__ __half g_kT [NB*HWSZ*CR];                       // [n][pos][c]
__device__ __half g_vh [NB*CR*HWSZ];                       // [n][c][pos]
__device__ __half g_attF[NB*HWSZ*CR];                      // [n][pos][c], x2^-15
__device__ float  g_partial[NB*NJT];

// ---------------- helpers (sm_80-level PTX only) ----------------------------
__device__ __forceinline__ uint32_t smem_u32(const void* p) {
    uint32_t a;
    asm("{ .reg .u64 t; cvta.to.shared.u64 t, %1; cvt.u32.u64 %0, t; }" : "=r"(a) : "l"(p));
    return a;
}
__device__ __forceinline__ void mma16816(float* d, const uint32_t* a, const uint32_t* b) {
    asm volatile("mma.sync.aligned.m16n8k16.row.col.f32.f16.f16.f32 "
        "{%0,%1,%2,%3}, {%4,%5,%6,%7}, {%8,%9}, {%0,%1,%2,%3};"
        : "+f"(d[0]), "+f"(d[1]), "+f"(d[2]), "+f"(d[3])
        : "r"(a[0]), "r"(a[1]), "r"(a[2]), "r"(a[3]), "r"(b[0]), "r"(b[1]));
}
__device__ __forceinline__ void ldsm_x4(uint32_t* r, uint32_t addr) {
    asm volatile("ldmatrix.sync.aligned.m8n8.x4.shared.b16 {%0,%1,%2,%3}, [%4];"
        : "=r"(r[0]), "=r"(r[1]), "=r"(r[2]), "=r"(r[3]) : "r"(addr));
}
__device__ __forceinline__ void ldsm_x4_t(uint32_t* r, uint32_t addr) {
    asm volatile("ldmatrix.sync.aligned.m8n8.x4.trans.shared.b16 {%0,%1,%2,%3}, [%4];"
        : "=r"(r[0]), "=r"(r[1]), "=r"(r[2]), "=r"(r[3]) : "r"(addr));
}
__device__ __forceinline__ void ldsm_x2(uint32_t* r, uint32_t addr) {
    asm volatile("ldmatrix.sync.aligned.m8n8.x2.shared.b16 {%0,%1}, [%2];"
        : "=r"(r[0]), "=r"(r[1]) : "r"(addr));
}
__device__ __forceinline__ void ldsm_x2_t(uint32_t* r, uint32_t addr) {
    asm volatile("ldmatrix.sync.aligned.m8n8.x2.trans.shared.b16 {%0,%1}, [%2];"
        : "=r"(r[0]), "=r"(r[1]) : "r"(addr));
}
__device__ __forceinline__ void cpa16(uint32_t dst, const void* src) {
    asm volatile("cp.async.cg.shared.global [%0], [%1], 16;" :: "r"(dst), "l"(src));
}
#define CPA_COMMIT() asm volatile("cp.async.commit_group;" ::: "memory")
#define CPA_WAIT0()  asm volatile("cp.async.wait_group 0;" ::: "memory")
#define CPA_WAIT1()  asm volatile("cp.async.wait_group 1;" ::: "memory")
__device__ __forceinline__ uint32_t pack_h2(float lo, float hi) {
    uint32_t r;
    asm("cvt.rn.f16x2.f32 %0, %1, %2;" : "=r"(r) : "f"(hi), "f"(lo));
    return r;
}
__device__ __forceinline__ uint32_t ex2_h2(uint32_t h) {
    uint32_t r;
    asm("ex2.approx.f16x2 %0, %1;" : "=r"(r) : "r"(h));
    return r;
}

// ---------------------------------------------------------------------------
// Kernel 0: x fp32 -> fp16, same [n][ci][p] layout. 8 elems/thread.
// ---------------------------------------------------------------------------
__global__ __launch_bounds__(256) void convert_kernel(const float* __restrict__ x)
{
    size_t i = ((size_t)blockIdx.x * 256 + threadIdx.x) * 8;
    float4 v0 = *(const float4*)(x + i);
    float4 v1 = *(const float4*)(x + i + 4);
    uint4 o;
    o.x = pack_h2(v0.x, v0.y);
    o.y = pack_h2(v0.z, v0.w);
    o.z = pack_h2(v1.x, v1.y);
    o.w = pack_h2(v1.z, v1.w);
    *(uint4*)&g_xh[i] = o;
}

// ---------------------------------------------------------------------------
// Kernel 1: HMMA QKV projection (single fp16).
//  which 0/1 (q,k): C[p][c] = x^T W^T, written transposed [pos][c]
//  which 2   (v)  : C[c][p] = W x,     written [c][pos]
// ---------------------------------------------------------------------------
#define XSTR 528
#define OFF_BIAS 0
#define OFF_WH   512
#define OFF_X    (OFF_WH + 64*XSTR)
#define XBUF(b)  (OFF_X + (b) * 64*XSTR)
#define QKV_SMEM (OFF_X + 2*64*XSTR)   // 101888

__global__ __launch_bounds__(256, 1) void qkv_hmma(
    const float* __restrict__ Wq, const float* __restrict__ bq,
    const float* __restrict__ Wk, const float* __restrict__ bk,
    const float* __restrict__ Wv, const float* __restrict__ bv)
{
    extern __shared__ char sm[];
    const uint32_t sb = smem_u32(sm);
    const int tid = threadIdx.x, wid = tid >> 5, lane = tid & 31;
    const int n = blockIdx.y, p0 = blockIdx.x * 256, which = blockIdx.z;

    const float* W = (which == 0) ? Wq : (which == 1) ? Wk : Wv;
    const float* b = (which == 0) ? bq : (which == 1) ? bk : bv;

    if (tid < 64) ((float*)(sm + OFF_BIAS))[tid] = b[tid];
    for (int t = tid; t < 64*256; t += 256) {
        int c = t >> 8, ci = t & 255;
        *(__half*)(sm + OFF_WH + c*XSTR + ci*2) = __float2half_rn(W[t]);
    }

    #define LOAD_X(KK, BUF) do {                                                      \
        for (int t = tid; t < 2048; t += 256) {                                       \
            int r = t >> 5, ch = t & 31;                                              \
            const char* src = (const char*)g_xh                                       \
                + ((size_t)(n*CIN + (KK)*64 + r)*HWSZ + p0)*2 + ch*16;                \
            cpa16(sb + XBUF(BUF) + r*XSTR + ch*16, src);                              \
        }                                                                             \
    } while (0)

    LOAD_X(0, 0);
    CPA_COMMIT();

    float acc[16][4];
    #pragma unroll
    for (int t = 0; t < 16; t++)
        #pragma unroll
        for (int r = 0; r < 4; r++) acc[t][r] = 0.f;

    for (int kk = 0; kk < 4; kk++) {
        const int buf = kk & 1;
        if (kk < 3) { LOAD_X(kk + 1, buf ^ 1); CPA_COMMIT(); CPA_WAIT1(); }
        else        { CPA_WAIT0(); }
        __syncthreads();

        const uint32_t xh = sb + XBUF(buf);

        if (which < 2) {
            #pragma unroll
            for (int k = 0; k < 4; k++) {
                const int ci = kk*64 + k*16;
                uint32_t bh[8][2];
                #pragma unroll
                for (int ni = 0; ni < 8; ni++) {
                    uint32_t a = (ni*8 + (lane&7))*XSTR + (ci + ((lane>>3)&1)*8)*2;
                    ldsm_x2(bh[ni], sb + OFF_WH + a);
                }
                #pragma unroll
                for (int mi = 0; mi < 2; mi++) {
                    uint32_t aH[4];
                    uint32_t ar = k*16 + (lane&7) + ((lane>>4)<<3);
                    uint32_t ac = wid*32 + mi*16 + ((lane>>3)&1)*8;
                    ldsm_x4_t(aH, xh + ar*XSTR + ac*2);
                    #pragma unroll
                    for (int ni = 0; ni < 8; ni++)
                        mma16816(acc[mi*8+ni], aH, bh[ni]);
                }
            }
        } else {
            #pragma unroll
            for (int k = 0; k < 4; k++) {
                const int ci = kk*64 + k*16;
                uint32_t bxh[4][2];
                #pragma unroll
                for (int ni = 0; ni < 4; ni++) {
                    uint32_t a = (k*16 + (lane&7) + ((lane>>3)&1)*8)*XSTR
                               + (wid*32 + ni*8)*2;
                    ldsm_x2_t(bxh[ni], xh + a);
                }
                #pragma unroll
                for (int mi = 0; mi < 4; mi++) {
                    uint32_t aH[4];
                    uint32_t a = (mi*16 + (lane&15))*XSTR + (ci + (lane>>4)*8)*2;
                    ldsm_x4(aH, sb + OFF_WH + a);
                    #pragma unroll
                    for (int ni = 0; ni < 4; ni++)
                        mma16816(acc[mi*4+ni], aH, bxh[ni]);
                }
            }
        }
        __syncthreads();
    }

    const float* sBias = (const float*)(sm + OFF_BIAS);

    if (which < 2) {
        __half* oh = (which == 0) ? g_qT : g_kT;
        char* stg = sm + XBUF(0) + wid*4608;
        #pragma unroll
        for (int mi = 0; mi < 2; mi++)
            #pragma unroll
            for (int ni = 0; ni < 8; ni++) {
                float b0 = sBias[ni*8 + (lane&3)*2];
                float b1 = sBias[ni*8 + (lane&3)*2 + 1];
                const float* d = acc[mi*8+ni];
                uint32_t u0 = pack_h2(d[0]+b0, d[1]+b1);
                uint32_t u1 = pack_h2(d[2]+b0, d[3]+b1);
                uint32_t cb = (ni*8 + (lane&3)*2)*2;
                *(uint32_t*)(stg + (mi*16 + (lane>>2))*144 + cb)     = u0;
                *(uint32_t*)(stg + (mi*16 + (lane>>2) + 8)*144 + cb) = u1;
            }
        __syncwarp();
        #pragma unroll
        for (int i = 0; i < 8; i++) {
            int chunk = i*32 + lane, row = chunk >> 3, off = chunk & 7;
            uint4 v = *(uint4*)(stg + row*144 + off*16);
            *(uint4*)&oh[((size_t)n*HWSZ + p0 + wid*32 + row)*CR + off*8] = v;
        }
    } else {
        #pragma unroll
        for (int mi = 0; mi < 4; mi++) {
            int c0 = mi*16 + (lane>>2), c1 = c0 + 8;
            float b0 = sBias[c0], b1 = sBias[c1];
            #pragma unroll
            for (int ni = 0; ni < 4; ni++) {
                const float* d = acc[mi*4+ni];
                size_t p = (size_t)p0 + wid*32 + ni*8 + (lane&3)*2;
                *(uint32_t*)&g_vh[((size_t)n*CR + c0)*HWSZ + p] = pack_h2(d[0]+b0, d[1]+b0);
                *(uint32_t*)&g_vh[((size_t)n*CR + c1)*HWSZ + p] = pack_h2(d[2]+b1, d[3]+b1);
            }
        }
    }
}

// ---------------------------------------------------------------------------
// Kernel 2: FA2-style HMMA attention.
//   MMA1: P = Q^T K  -> pack fp16 -> hfma2(p, log2e, -11) -> ex2.f16x2
//   lsum: extra MMA with ones B-fragment (row sums on tensor pipe, fp32 acc)
//   MMA2: attT += P V^T  (P A-frag direct from registers)
// ldsm_x4 for K and V fragments. 2 CTAs/SM.
// ---------------------------------------------------------------------------
#define QSTRIDE 144
#define VSTRIDE 272
#define SM_RED  0
#define SM_QH   128
#define SM_KH   (SM_QH + 128*QSTRIDE)
#define SM_VH   (SM_KH + 2*128*QSTRIDE)
#define SM_TOT  (SM_VH + 2*64*VSTRIDE)     // 90240

__global__ __launch_bounds__(256, 2) void attn_kernel()
{
    extern __shared__ char smem[];
    const uint32_t sb = smem_u32(smem);
    const int tid = threadIdx.x, wid = tid >> 5, lane = tid & 31;
    const int n = blockIdx.y, j0 = blockIdx.x * 128;

    {
        const char* qh = (const char*)(g_qT + ((size_t)n*HWSZ + j0)*CR);
        for (int t = tid; t < 1024; t += 256) {
            int row = t >> 3, ch = t & 7;
            cpa16(sb + SM_QH + row*QSTRIDE + ch*16, qh + row*128 + ch*16);
        }
    }
    const char* khg = (const char*)(g_kT + (size_t)n*HWSZ*CR);
    const char* vhg = (const char*)(g_vh + (size_t)n*CR*HWSZ);

    #define LOAD_KV(IT, BUF) do {                                                   \
        const int _i0 = (IT) * 128;                                                 \
        const uint32_t _kh = sb + SM_KH + (BUF)*128*QSTRIDE;                         \
        for (int t = tid; t < 1024; t += 256) {                                      \
            int row = t >> 3, ch = t & 7;                                            \
            cpa16(_kh + row*QSTRIDE + ch*16, khg + ((size_t)(_i0+row)*CR)*2 + ch*16);\
        }                                                                            \
        const uint32_t _vh = sb + SM_VH + (BUF)*64*VSTRIDE;                          \
        for (int t = tid; t < 1024; t += 256) {                                      \
            int c = t >> 4, ch = t & 15;                                             \
            cpa16(_vh + c*VSTRIDE + ch*16, vhg + ((size_t)c*HWSZ + _i0)*2 + ch*16);  \
        }                                                                            \
    } while (0)

    LOAD_KV(0, 0);
    CPA_COMMIT();
    CPA_WAIT0();
    __syncthreads();

    uint32_t qf[4][4];
    {
        const int jrow = wid*16 + (lane & 15);
        const int coff = ((lane >> 4) << 3);
        #pragma unroll
        for (int k = 0; k < 4; k++)
            ldsm_x4(qf[k], sb + SM_QH + jrow*QSTRIDE + (k*16 + coff)*2);
    }

    float accO[8][4];
    #pragma unroll
    for (int t = 0; t < 8; t++)
        #pragma unroll
        for (int r = 0; r < 4; r++) accO[t][r] = 0.f;
    float accS[4] = {0.f, 0.f, 0.f, 0.f};
    const uint32_t ones2[2] = {0x3C003C00u, 0x3C003C00u};   // half2(1.0, 1.0)

    const uint32_t l_row  = ((lane >> 4) << 3) + (lane & 7);
    const uint32_t l_half = ((lane >> 3) & 1) * 8;
    const __half2 l2e2 = __float2half2_rn(1.44269504f);
    const __half2 m112 = __float2half2_rn(-11.0f);

    #pragma unroll 1
    for (int it = 0; it < NITA; it++) {
        const int buf = it & 1;
        if (it + 1 < NITA) { LOAD_KV(it + 1, buf ^ 1); CPA_COMMIT(); CPA_WAIT1(); }
        else               { CPA_WAIT0(); }
        __syncthreads();

        const uint32_t khb = sb + SM_KH + buf*128*QSTRIDE;
        const uint32_t vhb = sb + SM_VH + buf*64*VSTRIDE;

        #pragma unroll
        for (int ic = 0; ic < 8; ic++) {
            uint32_t bk4[4][4];
            #pragma unroll
            for (int k = 0; k < 4; k++)
                ldsm_x4(bk4[k], khb + (ic*16 + l_row)*QSTRIDE + (k*16 + l_half)*2);

            float pacc[2][4];
            #pragma unroll
            for (int nt = 0; nt < 2; nt++)
                #pragma unroll
                for (int r = 0; r < 4; r++) pacc[nt][r] = 0.f;

            #pragma unroll
            for (int k = 0; k < 4; k++) {
                mma16816(pacc[0], qf[k], &bk4[k][0]);
                mma16816(pacc[1], qf[k], &bk4[k][2]);
            }

            // pack P to fp16 pairs, then exp in half2: e = exp2(p*log2e - 11)
            uint32_t af[4];
            af[0] = pack_h2(pacc[0][0], pacc[0][1]);
            af[1] = pack_h2(pacc[0][2], pacc[0][3]);
            af[2] = pack_h2(pacc[1][0], pacc[1][1]);
            af[3] = pack_h2(pacc[1][2], pacc[1][3]);
            #pragma unroll
            for (int g2 = 0; g2 < 4; g2++) {
                __half2 t = __hfma2(*(__half2*)&af[g2], l2e2, m112);
                af[g2] = ex2_h2(*(uint32_t*)&t);
            }

            // row sums of P via ones-MMA (fp32 accumulation on tensor pipe)
            mma16816(accS, af, ones2);

            #pragma unroll
            for (int t = 0; t < 4; t++) {
                uint32_t bv4[4];
                ldsm_x4(bv4, vhb + (t*16 + l_row)*VSTRIDE + (ic*16 + l_half)*2);
                mma16816(accO[t*2],     af, &bv4[0]);
                mma16816(accO[t*2 + 1], af, &bv4[2]);
            }
        }
        __syncthreads();
    }

    {
        int r0 = j0 + wid*16 + (lane >> 2);
        int c0 = (lane & 3) * 2;
        __half* base0 = g_attF + ((size_t)n*HWSZ + r0)*CR;
        __half* base1 = base0 + 8*CR;
        #pragma unroll
        for (int nt2 = 0; nt2 < 8; nt2++) {
            *(uint32_t*)&base0[nt2*8 + c0] = pack_h2(accO[nt2][0]*ASCALE, accO[nt2][1]*ASCALE);
            *(uint32_t*)&base1[nt2*8 + c0] = pack_h2(accO[nt2][2]*ASCALE, accO[nt2][3]*ASCALE);
        }
    }

    // lsum: accS columns are duplicated row sums; count one lane per quad
    float lsum = ((lane & 3) == 0) ? (accS[0] + accS[2]) : 0.f;
    #pragma unroll
    for (int off = 16; off > 0; off >>= 1)
        lsum += __shfl_xor_sync(0xFFFFFFFFu, lsum, off);
    if (lane == 0) ((float*)(smem + SM_RED))[wid] = lsum;
    __syncthreads();
    if (tid == 0) {
        float s = 0.f;
        #pragma unroll
        for (int w = 0; w < 8; w++) s += ((float*)(smem + SM_RED))[w];
        g_partial[n*NJT + blockIdx.x] = s;   // = S_true * 2^-11
    }
}

// ---------------------------------------------------------------------------
// Kernel 3: HMMA output conv + normalize + residual.
// out[o][p] = gco * (Watt@attF * 16/Sp + batt + 1)
// Tile 64o x 128p, grid (18, 4, 16), 2 CTAs/SM.
// gco prefetched into smem via cp.async (overlapped with MMA) so the epilogue
// has NO dependent DRAM loads — only smem reads + streaming float4 stores.
// ---------------------------------------------------------------------------
#define OW_STR 144
#define OST_F  132                          // stage row stride in floats
#define OO_S   0
#define OO_B   16
#define OO_W   288
#define OO_A   (OO_W + 64*OW_STR)           // 9504
#define OO_G   (OO_A + 128*OW_STR)          // 27936 ; gco 64 rows x 512 B
#define OO_ST  (OO_G + 64*512)              // 60704
#define OUT_SMEM (OO_ST + 64*OST_F*4)       // 94496

__global__ __launch_bounds__(256, 2) void out_hmma(
    const float* __restrict__ gco,
    const float* __restrict__ Watt, const float* __restrict__ batt,
    float* __restrict__ out)
{
    extern __shared__ char sm[];
    const uint32_t sb = smem_u32(sm);
    const int tid = threadIdx.x, wid = tid >> 5, lane = tid & 31;
    const int n = blockIdx.z, o0 = blockIdx.y * 64, p0 = blockIdx.x * 128;

    if (tid == 0) {
        float s = 0.f;
        #pragma unroll
        for (int t = 0; t < NJT; t++) s += g_partial[n*NJT + t];
        *(float*)(sm + OO_S) = 16.0f / s;
    }
    if (tid < 64) ((float*)(sm + OO_B))[tid] = batt[o0 + tid];
    for (int t = tid; t < 64*64; t += 256) {
        int o = t >> 6, c = t & 63;
        *(__half*)(sm + OO_W + o*OW_STR + c*2) =
            __float2half_rn(Watt[(size_t)(o0 + o)*CR + c]);
    }
    // group A: att fp16 -> smem [p][c]
    {
        const char* ag = (const char*)(g_attF + ((size_t)n*HWSZ + p0)*CR);
        for (int t = tid; t < 1024; t += 256) {
            int r = t >> 3, ch = t & 7;
            cpa16(sb + OO_A + r*OW_STR + ch*16, ag + r*128 + ch*16);
        }
    }
    CPA_COMMIT();
    // group B: gco tile 64o x 128p fp32 -> smem (consumed only in epilogue)
    {
        const char* gg = (const char*)(gco + ((size_t)n*CIN + o0)*HWSZ + p0);
        for (int t = tid; t < 2048; t += 256) {
            int r = t >> 5, ch = t & 31;
            cpa16(sb + OO_G + r*512 + ch*16, gg + (size_t)r*HWSZ*4 + ch*16);
        }
    }
    CPA_COMMIT();
    CPA_WAIT1();            // attF ready; gco still in flight
    __syncthreads();

    const int wo = wid & 1, wp = wid >> 1;   // 2 warps over o(32), 4 over p(32)
    const uint32_t l_row  = ((lane >> 4) << 3) + (lane & 7);
    const uint32_t l_half = ((lane >> 3) & 1) * 8;

    float acc[8][4];
    #pragma unroll
    for (int t = 0; t < 8; t++)
        #pragma unroll
        for (int r = 0; r < 4; r++) acc[t][r] = 0.f;

    #pragma unroll
    for (int k = 0; k < 4; k++) {
        uint32_t bA[8];
        #pragma unroll
        for (int t2 = 0; t2 < 2; t2++)
            ldsm_x4(&bA[t2*4], sb + OO_A + (wp*32 + t2*16 + l_row)*OW_STR
                                         + (k*16 + l_half)*2);
        #pragma unroll
        for (int mi = 0; mi < 2; mi++) {
            uint32_t aW[4];
            ldsm_x4(aW, sb + OO_W + (wo*32 + mi*16 + (lane&15))*OW_STR
                                  + (k*16 + ((lane>>4)<<3))*2);
            #pragma unroll
            for (int ni = 0; ni < 4; ni++)
                mma16816(acc[mi*4+ni], aW, &bA[ni*2]);
        }
    }

    // stage fp32 accumulators: stage[o_local][p_local], stride OST_F floats
    float* stg = (float*)(sm + OO_ST);
    #pragma unroll
    for (int mi = 0; mi < 2; mi++)
        #pragma unroll
        for (int ni = 0; ni < 4; ni++) {
            const float* d = acc[mi*4+ni];
            int c = wp*32 + ni*8 + (lane&3)*2;
            int r = wo*32 + mi*16 + (lane>>2);
            *(float2*)&stg[r*OST_F + c]       = make_float2(d[0], d[1]);
            *(float2*)&stg[(r+8)*OST_F + c]   = make_float2(d[2], d[3]);
        }
    CPA_WAIT0();            // gco landed
    __syncthreads();

    const float oscale = *(const float*)(sm + OO_S);
    const float* sB = (const float*)(sm + OO_B);
    const float* sG = (const float*)(sm + OO_G);

    // one warp = one 512B row: smem reads only + streaming float4 stores
    #pragma unroll
    for (int i = 0; i < 8; i++) {
        int row = i*8 + wid;                 // local o row 0..63
        int col = lane*4;                    // local p col
        float4 a = *(float4*)&stg[row*OST_F + col];
        float4 g = *(const float4*)&sG[row*128 + col];
        float bias = sB[row] + 1.f;
        size_t gb = ((size_t)n*CIN + o0 + row)*HWSZ + p0 + col;
        float4 rr;
        rr.x = g.x * fmaf(a.x, oscale, bias);
        rr.y = g.y * fmaf(a.y, oscale, bias);
        rr.z = g.z * fmaf(a.z, oscale, bias);
        rr.w = g.w * fmaf(a.w, oscale, bias);
        *(float4*)&out[gb] = rr;
    }
}

// ---------------------------------------------------------------------------
extern "C" void kernel_launch(void* const* d_in, const int* in_sizes, int n_in,
                              void* d_out, int out_size)
{
    const float* x    = (const float*)d_in[0];
    const float* gco  = (const float*)d_in[1];
    const float* Wq   = (const float*)d_in[2];
    const float* bq   = (const float*)d_in[3];
    const float* Wk   = (const float*)d_in[4];
    const float* bk   = (const float*)d_in[5];
    const float* Wv   = (const float*)d_in[6];
    const float* bv   = (const float*)d_in[7];
    const float* Watt = (const float*)d_in[8];
    const float* batt = (const float*)d_in[9];
    float* out = (float*)d_out;

    cudaFuncSetAttribute(qkv_hmma,    cudaFuncAttributeMaxDynamicSharedMemorySize, QKV_SMEM);
    cudaFuncSetAttribute(attn_kernel, cudaFuncAttributeMaxDynamicSharedMemorySize, SM_TOT);
    cudaFuncSetAttribute(out_hmma,    cudaFuncAttributeMaxDynamicSharedMemorySize, OUT_SMEM);

    convert_kernel<<<NB*CIN*HWSZ/2048, 256>>>(x);
    qkv_hmma<<<dim3(9, NB, 3), 256, QKV_SMEM>>>(Wq, bq, Wk, bk, Wv, bv);
    attn_kernel<<<dim3(NJT, NB), 256, SM_TOT>>>();
    out_hmma<<<dim3(18, 4, NB), 256, OUT_SMEM>>>(gco, Watt, batt, out);
}

// round 17
// speedup vs baseline: 1.1498x; 1.0961x over previous
#include <cuda_runtime.h>
#include <cuda_fp16.h>
#include <cstdint>

#define NB   16
#define CIN  256
#define CR   64
#define HWSZ 2304
#define NJT  18            // 2304 / 128 j tiles (attn)
#define NITA 18            // attn i tiles of 128

// exp path: e = exp2(p*log2e - 11) = exp(p) * 2^-11 (P scale folded into exponent)
// att stored fp16 with extra 2^-4; lsum sums e (scaled 2^-11) -> oscale = 16/Sp
#define ASCALE  0.0625f

// ---------------- scratch (device globals; no allocation allowed) ----------
__device__ __half g_xh [NB*CIN*HWSZ];                      // x fp16
__device__ __half g_qT [NB*HWSZ*CR];                       // [n][pos][c]
__device__ __half g_kT [NB*HWSZ*CR];                       // [n][pos][c]
__device__ __half g_vh [NB*CR*HWSZ];                       // [n][c][pos]
__device__ __half g_attF[NB*HWSZ*CR];                      // [n][pos][c], x2^-15
__device__ float  g_partial[NB*NJT];

// ---------------- helpers (sm_80-level PTX only) ----------------------------
__device__ __forceinline__ uint32_t smem_u32(const void* p) {
    uint32_t a;
    asm("{ .reg .u64 t; cvta.to.shared.u64 t, %1; cvt.u32.u64 %0, t; }" : "=r"(a) : "l"(p));
    return a;
}
__device__ __forceinline__ void mma16816(float* d, const uint32_t* a, const uint32_t* b) {
    asm volatile("mma.sync.aligned.m16n8k16.row.col.f32.f16.f16.f32 "
        "{%0,%1,%2,%3}, {%4,%5,%6,%7}, {%8,%9}, {%0,%1,%2,%3};"
        : "+f"(d[0]), "+f"(d[1]), "+f"(d[2]), "+f"(d[3])
        : "r"(a[0]), "r"(a[1]), "r"(a[2]), "r"(a[3]), "r"(b[0]), "r"(b[1]));
}
__device__ __forceinline__ void ldsm_x4(uint32_t* r, uint32_t addr) {
    asm volatile("ldmatrix.sync.aligned.m8n8.x4.shared.b16 {%0,%1,%2,%3}, [%4];"
        : "=r"(r[0]), "=r"(r[1]), "=r"(r[2]), "=r"(r[3]) : "r"(addr));
}
__device__ __forceinline__ void ldsm_x4_t(uint32_t* r, uint32_t addr) {
    asm volatile("ldmatrix.sync.aligned.m8n8.x4.trans.shared.b16 {%0,%1,%2,%3}, [%4];"
        : "=r"(r[0]), "=r"(r[1]), "=r"(r[2]), "=r"(r[3]) : "r"(addr));
}
__device__ __forceinline__ void ldsm_x2(uint32_t* r, uint32_t addr) {
    asm volatile("ldmatrix.sync.aligned.m8n8.x2.shared.b16 {%0,%1}, [%2];"
        : "=r"(r[0]), "=r"(r[1]) : "r"(addr));
}
__device__ __forceinline__ void ldsm_x2_t(uint32_t* r, uint32_t addr) {
    asm volatile("ldmatrix.sync.aligned.m8n8.x2.trans.shared.b16 {%0,%1}, [%2];"
        : "=r"(r[0]), "=r"(r[1]) : "r"(addr));
}
__device__ __forceinline__ void cpa16(uint32_t dst, const void* src) {
    asm volatile("cp.async.cg.shared.global [%0], [%1], 16;" :: "r"(dst), "l"(src));
}
#define CPA_COMMIT() asm volatile("cp.async.commit_group;" ::: "memory")
#define CPA_WAIT0()  asm volatile("cp.async.wait_group 0;" ::: "memory")
#define CPA_WAIT1()  asm volatile("cp.async.wait_group 1;" ::: "memory")
__device__ __forceinline__ uint32_t pack_h2(float lo, float hi) {
    uint32_t r;
    asm("cvt.rn.f16x2.f32 %0, %1, %2;" : "=r"(r) : "f"(hi), "f"(lo));
    return r;
}
__device__ __forceinline__ uint32_t ex2_h2(uint32_t h) {
    uint32_t r;
    asm("ex2.approx.f16x2 %0, %1;" : "=r"(r) : "r"(h));
    return r;
}

// ---------------------------------------------------------------------------
// Kernel 0: x fp32 -> fp16, same [n][ci][p] layout. 8 elems/thread.
// ---------------------------------------------------------------------------
__global__ __launch_bounds__(256) void convert_kernel(const float* __restrict__ x)
{
    size_t i = ((size_t)blockIdx.x * 256 + threadIdx.x) * 8;
    float4 v0 = *(const float4*)(x + i);
    float4 v1 = *(const float4*)(x + i + 4);
    uint4 o;
    o.x = pack_h2(v0.x, v0.y);
    o.y = pack_h2(v0.z, v0.w);
    o.z = pack_h2(v1.x, v1.y);
    o.w = pack_h2(v1.z, v1.w);
    *(uint4*)&g_xh[i] = o;
}

// ---------------------------------------------------------------------------
// Kernel 1: HMMA QKV projection (single fp16). 2 CTAs/SM.
//  which 0/1 (q,k): C[p][c] = x^T W^T, written transposed [pos][c]
//  which 2   (v)  : C[c][p] = W x,     written [c][pos]
// ---------------------------------------------------------------------------
#define XSTR 528
#define OFF_BIAS 0
#define OFF_WH   512
#define OFF_X    (OFF_WH + 64*XSTR)
#define XBUF(b)  (OFF_X + (b) * 64*XSTR)
#define QKV_SMEM (OFF_X + 2*64*XSTR)   // 101888

__global__ __launch_bounds__(256, 2) void qkv_hmma(
    const float* __restrict__ Wq, const float* __restrict__ bq,
    const float* __restrict__ Wk, const float* __restrict__ bk,
    const float* __restrict__ Wv, const float* __restrict__ bv)
{
    extern __shared__ char sm[];
    const uint32_t sb = smem_u32(sm);
    const int tid = threadIdx.x, wid = tid >> 5, lane = tid & 31;
    const int n = blockIdx.y, p0 = blockIdx.x * 256, which = blockIdx.z;

    const float* W = (which == 0) ? Wq : (which == 1) ? Wk : Wv;
    const float* b = (which == 0) ? bq : (which == 1) ? bk : bv;

    if (tid < 64) ((float*)(sm + OFF_BIAS))[tid] = b[tid];
    for (int t = tid; t < 64*256; t += 256) {
        int c = t >> 8, ci = t & 255;
        *(__half*)(sm + OFF_WH + c*XSTR + ci*2) = __float2half_rn(W[t]);
    }

    #define LOAD_X(KK, BUF) do {                                                      \
        for (int t = tid; t < 2048; t += 256) {                                       \
            int r = t >> 5, ch = t & 31;                                              \
            const char* src = (const char*)g_xh                                       \
                + ((size_t)(n*CIN + (KK)*64 + r)*HWSZ + p0)*2 + ch*16;                \
            cpa16(sb + XBUF(BUF) + r*XSTR + ch*16, src);                              \
        }                                                                             \
    } while (0)

    LOAD_X(0, 0);
    CPA_COMMIT();

    float acc[16][4];
    #pragma unroll
    for (int t = 0; t < 16; t++)
        #pragma unroll
        for (int r = 0; r < 4; r++) acc[t][r] = 0.f;

    for (int kk = 0; kk < 4; kk++) {
        const int buf = kk & 1;
        if (kk < 3) { LOAD_X(kk + 1, buf ^ 1); CPA_COMMIT(); CPA_WAIT1(); }
        else        { CPA_WAIT0(); }
        __syncthreads();

        const uint32_t xh = sb + XBUF(buf);

        if (which < 2) {
            #pragma unroll
            for (int k = 0; k < 4; k++) {
                const int ci = kk*64 + k*16;
                uint32_t bh[8][2];
                #pragma unroll
                for (int ni = 0; ni < 8; ni++) {
                    uint32_t a = (ni*8 + (lane&7))*XSTR + (ci + ((lane>>3)&1)*8)*2;
                    ldsm_x2(bh[ni], sb + OFF_WH + a);
                }
                #pragma unroll
                for (int mi = 0; mi < 2; mi++) {
                    uint32_t aH[4];
                    uint32_t ar = k*16 + (lane&7) + ((lane>>4)<<3);
                    uint32_t ac = wid*32 + mi*16 + ((lane>>3)&1)*8;
                    ldsm_x4_t(aH, xh + ar*XSTR + ac*2);
                    #pragma unroll
                    for (int ni = 0; ni < 8; ni++)
                        mma16816(acc[mi*8+ni], aH, bh[ni]);
                }
            }
        } else {
            #pragma unroll
            for (int k = 0; k < 4; k++) {
                const int ci = kk*64 + k*16;
                uint32_t bxh[4][2];
                #pragma unroll
                for (int ni = 0; ni < 4; ni++) {
                    uint32_t a = (k*16 + (lane&7) + ((lane>>3)&1)*8)*XSTR
                               + (wid*32 + ni*8)*2;
                    ldsm_x2_t(bxh[ni], xh + a);
                }
                #pragma unroll
                for (int mi = 0; mi < 4; mi++) {
                    uint32_t aH[4];
                    uint32_t a = (mi*16 + (lane&15))*XSTR + (ci + (lane>>4)*8)*2;
                    ldsm_x4(aH, sb + OFF_WH + a);
                    #pragma unroll
                    for (int ni = 0; ni < 4; ni++)
                        mma16816(acc[mi*4+ni], aH, bxh[ni]);
                }
            }
        }
        __syncthreads();
    }

    const float* sBias = (const float*)(sm + OFF_BIAS);

    if (which < 2) {
        __half* oh = (which == 0) ? g_qT : g_kT;
        char* stg = sm + XBUF(0) + wid*4608;
        #pragma unroll
        for (int mi = 0; mi < 2; mi++)
            #pragma unroll
            for (int ni = 0; ni < 8; ni++) {
                float b0 = sBias[ni*8 + (lane&3)*2];
                float b1 = sBias[ni*8 + (lane&3)*2 + 1];
                const float* d = acc[mi*8+ni];
                uint32_t u0 = pack_h2(d[0]+b0, d[1]+b1);
                uint32_t u1 = pack_h2(d[2]+b0, d[3]+b1);
                uint32_t cb = (ni*8 + (lane&3)*2)*2;
                *(uint32_t*)(stg + (mi*16 + (lane>>2))*144 + cb)     = u0;
                *(uint32_t*)(stg + (mi*16 + (lane>>2) + 8)*144 + cb) = u1;
            }
        __syncwarp();
        #pragma unroll
        for (int i = 0; i < 8; i++) {
            int chunk = i*32 + lane, row = chunk >> 3, off = chunk & 7;
            uint4 v = *(uint4*)(stg + row*144 + off*16);
            *(uint4*)&oh[((size_t)n*HWSZ + p0 + wid*32 + row)*CR + off*8] = v;
        }
    } else {
        #pragma unroll
        for (int mi = 0; mi < 4; mi++) {
            int c0 = mi*16 + (lane>>2), c1 = c0 + 8;
            float b0 = sBias[c0], b1 = sBias[c1];
            #pragma unroll
            for (int ni = 0; ni < 4; ni++) {
                const float* d = acc[mi*4+ni];
                size_t p = (size_t)p0 + wid*32 + ni*8 + (lane&3)*2;
                *(uint32_t*)&g_vh[((size_t)n*CR + c0)*HWSZ + p] = pack_h2(d[0]+b0, d[1]+b0);
                *(uint32_t*)&g_vh[((size_t)n*CR + c1)*HWSZ + p] = pack_h2(d[2]+b1, d[3]+b1);
            }
        }
    }
}

// ---------------------------------------------------------------------------
// Kernel 2: FA2-style HMMA attention (unchanged from round 16).
//   MMA1: P = Q^T K  -> pack fp16 -> hfma2(p, log2e, -11) -> ex2.f16x2
//   lsum: extra MMA with ones B-fragment (row sums on tensor pipe, fp32 acc)
//   MMA2: attT += P V^T  (P A-frag direct from registers)
// ---------------------------------------------------------------------------
#define QSTRIDE 144
#define VSTRIDE 272
#define SM_RED  0
#define SM_QH   128
#define SM_KH   (SM_QH + 128*QSTRIDE)
#define SM_VH   (SM_KH + 2*128*QSTRIDE)
#define SM_TOT  (SM_VH + 2*64*VSTRIDE)     // 90240

__global__ __launch_bounds__(256, 2) void attn_kernel()
{
    extern __shared__ char smem[];
    const uint32_t sb = smem_u32(smem);
    const int tid = threadIdx.x, wid = tid >> 5, lane = tid & 31;
    const int n = blockIdx.y, j0 = blockIdx.x * 128;

    {
        const char* qh = (const char*)(g_qT + ((size_t)n*HWSZ + j0)*CR);
        for (int t = tid; t < 1024; t += 256) {
            int row = t >> 3, ch = t & 7;
            cpa16(sb + SM_QH + row*QSTRIDE + ch*16, qh + row*128 + ch*16);
        }
    }
    const char* khg = (const char*)(g_kT + (size_t)n*HWSZ*CR);
    const char* vhg = (const char*)(g_vh + (size_t)n*CR*HWSZ);

    #define LOAD_KV(IT, BUF) do {                                                   \
        const int _i0 = (IT) * 128;                                                 \
        const uint32_t _kh = sb + SM_KH + (BUF)*128*QSTRIDE;                         \
        for (int t = tid; t < 1024; t += 256) {                                      \
            int row = t >> 3, ch = t & 7;                                            \
            cpa16(_kh + row*QSTRIDE + ch*16, khg + ((size_t)(_i0+row)*CR)*2 + ch*16);\
        }                                                                            \
        const uint32_t _vh = sb + SM_VH + (BUF)*64*VSTRIDE;                          \
        for (int t = tid; t < 1024; t += 256) {                                      \
            int c = t >> 4, ch = t & 15;                                             \
            cpa16(_vh + c*VSTRIDE + ch*16, vhg + ((size_t)c*HWSZ + _i0)*2 + ch*16);  \
        }                                                                            \
    } while (0)

    LOAD_KV(0, 0);
    CPA_COMMIT();
    CPA_WAIT0();
    __syncthreads();

    uint32_t qf[4][4];
    {
        const int jrow = wid*16 + (lane & 15);
        const int coff = ((lane >> 4) << 3);
        #pragma unroll
        for (int k = 0; k < 4; k++)
            ldsm_x4(qf[k], sb + SM_QH + jrow*QSTRIDE + (k*16 + coff)*2);
    }

    float accO[8][4];
    #pragma unroll
    for (int t = 0; t < 8; t++)
        #pragma unroll
        for (int r = 0; r < 4; r++) accO[t][r] = 0.f;
    float accS[4] = {0.f, 0.f, 0.f, 0.f};
    const uint32_t ones2[2] = {0x3C003C00u, 0x3C003C00u};   // half2(1.0, 1.0)

    const uint32_t l_row  = ((lane >> 4) << 3) + (lane & 7);
    const uint32_t l_half = ((lane >> 3) & 1) * 8;
    const __half2 l2e2 = __float2half2_rn(1.44269504f);
    const __half2 m112 = __float2half2_rn(-11.0f);

    #pragma unroll 1
    for (int it = 0; it < NITA; it++) {
        const int buf = it & 1;
        if (it + 1 < NITA) { LOAD_KV(it + 1, buf ^ 1); CPA_COMMIT(); CPA_WAIT1(); }
        else               { CPA_WAIT0(); }
        __syncthreads();

        const uint32_t khb = sb + SM_KH + buf*128*QSTRIDE;
        const uint32_t vhb = sb + SM_VH + buf*64*VSTRIDE;

        #pragma unroll
        for (int ic = 0; ic < 8; ic++) {
            uint32_t bk4[4][4];
            #pragma unroll
            for (int k = 0; k < 4; k++)
                ldsm_x4(bk4[k], khb + (ic*16 + l_row)*QSTRIDE + (k*16 + l_half)*2);

            float pacc[2][4];
            #pragma unroll
            for (int nt = 0; nt < 2; nt++)
                #pragma unroll
                for (int r = 0; r < 4; r++) pacc[nt][r] = 0.f;

            #pragma unroll
            for (int k = 0; k < 4; k++) {
                mma16816(pacc[0], qf[k], &bk4[k][0]);
                mma16816(pacc[1], qf[k], &bk4[k][2]);
            }

            uint32_t af[4];
            af[0] = pack_h2(pacc[0][0], pacc[0][1]);
            af[1] = pack_h2(pacc[0][2], pacc[0][3]);
            af[2] = pack_h2(pacc[1][0], pacc[1][1]);
            af[3] = pack_h2(pacc[1][2], pacc[1][3]);
            #pragma unroll
            for (int g2 = 0; g2 < 4; g2++) {
                __half2 t = __hfma2(*(__half2*)&af[g2], l2e2, m112);
                af[g2] = ex2_h2(*(uint32_t*)&t);
            }

            mma16816(accS, af, ones2);

            #pragma unroll
            for (int t = 0; t < 4; t++) {
                uint32_t bv4[4];
                ldsm_x4(bv4, vhb + (t*16 + l_row)*VSTRIDE + (ic*16 + l_half)*2);
                mma16816(accO[t*2],     af, &bv4[0]);
                mma16816(accO[t*2 + 1], af, &bv4[2]);
            }
        }
        __syncthreads();
    }

    {
        int r0 = j0 + wid*16 + (lane >> 2);
        int c0 = (lane & 3) * 2;
        __half* base0 = g_attF + ((size_t)n*HWSZ + r0)*CR;
        __half* base1 = base0 + 8*CR;
        #pragma unroll
        for (int nt2 = 0; nt2 < 8; nt2++) {
            *(uint32_t*)&base0[nt2*8 + c0] = pack_h2(accO[nt2][0]*ASCALE, accO[nt2][1]*ASCALE);
            *(uint32_t*)&base1[nt2*8 + c0] = pack_h2(accO[nt2][2]*ASCALE, accO[nt2][3]*ASCALE);
        }
    }

    float lsum = ((lane & 3) == 0) ? (accS[0] + accS[2]) : 0.f;
    #pragma unroll
    for (int off = 16; off > 0; off >>= 1)
        lsum += __shfl_xor_sync(0xFFFFFFFFu, lsum, off);
    if (lane == 0) ((float*)(smem + SM_RED))[wid] = lsum;
    __syncthreads();
    if (tid == 0) {
        float s = 0.f;
        #pragma unroll
        for (int w = 0; w < 8; w++) s += ((float*)(smem + SM_RED))[w];
        g_partial[n*NJT + blockIdx.x] = s;   // = S_true * 2^-11
    }
}

// ---------------------------------------------------------------------------
// Kernel 3: HMMA output conv + normalize + residual.
// out[o][p] = gco * (Watt@attF * 16/Sp + batt + 1)
// Tile 128o x 128p (round-13 shape), grid (18, 2, 16) = 576, 2 CTAs/SM
// (reg-capped). Direct float2 epilogue (32B sector per quad).
// ---------------------------------------------------------------------------
#define OW_STR 144
#define OO_S   0
#define OO_B   16                           // 128 bias floats
#define OO_W   544
#define OO_A   (OO_W + 128*OW_STR)          // 18976
#define OUT_SMEM (OO_A + 128*OW_STR)        // 37408

__global__ __launch_bounds__(256, 2) void out_hmma(
    const float* __restrict__ gco,
    const float* __restrict__ Watt, const float* __restrict__ batt,
    float* __restrict__ out)
{
    extern __shared__ char sm[];
    const uint32_t sb = smem_u32(sm);
    const int tid = threadIdx.x, wid = tid >> 5, lane = tid & 31;
    const int n = blockIdx.z, o0 = blockIdx.y * 128, p0 = blockIdx.x * 128;

    if (tid == 0) {
        float s = 0.f;
        #pragma unroll
        for (int t = 0; t < NJT; t++) s += g_partial[n*NJT + t];
        *(float*)(sm + OO_S) = 16.0f / s;
    }
    if (tid < 128) ((float*)(sm + OO_B))[tid] = batt[o0 + tid];
    // Watt slice fp32 -> fp16 smem [o][c]
    for (int t = tid; t < 128*64; t += 256) {
        int o = t >> 6, c = t & 63;
        *(__half*)(sm + OO_W + o*OW_STR + c*2) =
            __float2half_rn(Watt[(size_t)(o0 + o)*CR + c]);
    }
    // att fp16 -> smem [p][c]
    {
        const char* ag = (const char*)(g_attF + ((size_t)n*HWSZ + p0)*CR);
        for (int t = tid; t < 1024; t += 256) {
            int r = t >> 3, ch = t & 7;
            cpa16(sb + OO_A + r*OW_STR + ch*16, ag + r*128 + ch*16);
        }
    }
    CPA_COMMIT();
    CPA_WAIT0();
    __syncthreads();

    const int wo = wid & 1, wp = wid >> 1;   // 2 warps over o(64), 4 over p(32)
    const uint32_t l_row  = ((lane >> 4) << 3) + (lane & 7);
    const uint32_t l_half = ((lane >> 3) & 1) * 8;

    float acc[16][4];
    #pragma unroll
    for (int t = 0; t < 16; t++)
        #pragma unroll
        for (int r = 0; r < 4; r++) acc[t][r] = 0.f;

    #pragma unroll
    for (int k = 0; k < 4; k++) {
        uint32_t bA[8];
        #pragma unroll
        for (int t2 = 0; t2 < 2; t2++)
            ldsm_x4(&bA[t2*4], sb + OO_A + (wp*32 + t2*16 + l_row)*OW_STR
                                         + (k*16 + l_half)*2);
        #pragma unroll
        for (int mi = 0; mi < 4; mi++) {
            uint32_t aW[4];
            ldsm_x4(aW, sb + OO_W + (wo*64 + mi*16 + (lane&15))*OW_STR
                                  + (k*16 + ((lane>>4)<<3))*2);
            #pragma unroll
            for (int ni = 0; ni < 4; ni++)
                mma16816(acc[mi*4+ni], aW, &bA[ni*2]);
        }
    }

    const float oscale = *(const float*)(sm + OO_S);
    const float* sB = (const float*)(sm + OO_B);

    // direct epilogue: each quad covers one 32B sector (8 consecutive floats)
    #pragma unroll
    for (int mi = 0; mi < 4; mi++)
        #pragma unroll
        for (int ni = 0; ni < 4; ni++) {
            const float* d = acc[mi*4+ni];
            int p = wp*32 + ni*8 + (lane&3)*2;
            #pragma unroll
            for (int h = 0; h < 2; h++) {
                int r = wo*64 + mi*16 + (lane>>2) + h*8;
                float bias = sB[r] + 1.f;
                size_t gb = ((size_t)n*CIN + o0 + r)*HWSZ + p0 + p;
                float2 g = *(const float2*)&gco[gb];
                float2 rr;
                rr.x = g.x * fmaf(d[h*2],   oscale, bias);
                rr.y = g.y * fmaf(d[h*2+1], oscale, bias);
                *(float2*)&out[gb] = rr;
            }
        }
}

// ---------------------------------------------------------------------------
extern "C" void kernel_launch(void* const* d_in, const int* in_sizes, int n_in,
                              void* d_out, int out_size)
{
    const float* x    = (const float*)d_in[0];
    const float* gco  = (const float*)d_in[1];
    const float* Wq   = (const float*)d_in[2];
    const float* bq   = (const float*)d_in[3];
    const float* Wk   = (const float*)d_in[4];
    const float* bk   = (const float*)d_in[5];
    const float* Wv   = (const float*)d_in[6];
    const float* bv   = (const float*)d_in[7];
    const float* Watt = (const float*)d_in[8];
    const float* batt = (const float*)d_in[9];
    float* out = (float*)d_out;

    cudaFuncSetAttribute(qkv_hmma,    cudaFuncAttributeMaxDynamicSharedMemorySize, QKV_SMEM);
    cudaFuncSetAttribute(attn_kernel, cudaFuncAttributeMaxDynamicSharedMemorySize, SM_TOT);
    cudaFuncSetAttribute(out_hmma,    cudaFuncAttributeMaxDynamicSharedMemorySize, OUT_SMEM);

    convert_kernel<<<NB*CIN*HWSZ/2048, 256>>>(x);
    qkv_hmma<<<dim3(9, NB, 3), 256, QKV_SMEM>>>(Wq, bq, Wk, bk, Wv, bv);
    attn_kernel<<<dim3(NJT, NB), 256, SM_TOT>>>();
    out_hmma<<<dim3(18, 2, NB), 256, OUT_SMEM>>>(gco, Watt, batt, out);
}